// round 2
// baseline (speedup 1.0000x reference)
#include <cuda_runtime.h>

#define NN 50000
#define NE 800000
#define DD 256

// ---------------- scratch (no allocations allowed) ----------------
__device__ float g_x[NN * DD];    // current node features
__device__ float g_g[NN * DD];    // g = dinv * (x @ W)
__device__ float g_acc[NN * DD];  // aggregation accumulator
__device__ float g_deg[NN];       // degree -> dinv (in place)
__device__ int   g_src[NE];
__device__ int   g_dst[NE];
__device__ int   g_is64;

// ---------------- edge-index dtype sniffing + conversion ----------------
// If edge_index is int64 (values in [0,50000)), all odd 32-bit words are 0.
// If int32, odd words are random indices -> essentially never all zero.
__global__ void detect_dtype(const unsigned int* __restrict__ w) {
    __shared__ int any_nz;
    if (threadIdx.x == 0) any_nz = 0;
    __syncthreads();
    int nz = 0;
#pragma unroll
    for (int i = 0; i < 16; i++) {
        int idx = (threadIdx.x * 16 + i) * 2 + 1;  // odd dwords, first 8192 dwords
        if (w[idx] != 0u) nz = 1;
    }
    if (nz) atomicOr(&any_nz, 1);
    __syncthreads();
    if (threadIdx.x == 0) g_is64 = any_nz ? 0 : 1;
}

__global__ void deg_init(float* deg) {
    int i = blockIdx.x * blockDim.x + threadIdx.x;
    if (i < NN) deg[i] = 1.0f;  // self loop
}

// convert to int32 src/dst and count in-degrees in one pass
__global__ void convert_and_count(const unsigned int* __restrict__ w,
                                  int* __restrict__ src, int* __restrict__ dst,
                                  float* __restrict__ deg) {
    int e = blockIdx.x * blockDim.x + threadIdx.x;
    if (e >= NE) return;
    int s, d;
    if (g_is64) {
        s = (int)w[2 * e];
        d = (int)w[2 * NE + 2 * e];
    } else {
        s = (int)w[e];
        d = (int)w[NE + e];
    }
    src[e] = s;
    dst[e] = d;
    atomicAdd(&deg[d], 1.0f);
}

__global__ void deg_inv(float* deg) {
    int i = blockIdx.x * blockDim.x + threadIdx.x;
    if (i < NN) deg[i] = rsqrtf(deg[i]);
}

// ---------------- SGEMM: C = A[M,256] @ B[256,256] ----------------
// MODE 0: O1 = relu(C + bias)
// MODE 1: g = dinv[m] * C; O1 = g; O2 = g  (acc init = self-loop term)
template <int MODE>
__global__ void __launch_bounds__(256) sgemm(
    const float* __restrict__ A, const float* __restrict__ B,
    const float* __restrict__ bias, const float* __restrict__ dinv,
    float* __restrict__ O1, float* __restrict__ O2, int M)
{
    constexpr int BM = 128, BN = 128, BK = 16, LDA = 132;
    __shared__ float As[BK * LDA];
    __shared__ float Bs[BK * BN];

    const int tid = threadIdx.x;
    const int tx = tid & 15;        // 0..15 -> col groups of 8
    const int ty = tid >> 4;        // 0..15 -> row groups of 8
    const int brow = blockIdx.y * BM;
    const int bcol = blockIdx.x * BN;

    float acc[8][8];
#pragma unroll
    for (int i = 0; i < 8; i++)
#pragma unroll
        for (int j = 0; j < 8; j++) acc[i][j] = 0.0f;

    for (int kk = 0; kk < 256; kk += BK) {
        // load A tile (BM x BK), store transposed to As[BK][LDA]
#pragma unroll
        for (int it = 0; it < 2; it++) {
            int id = it * 256 + tid;          // 0..511 float4 slots
            int r = id >> 2;                  // 0..127
            int c4 = id & 3;                  // 0..3
            float4 v = make_float4(0.f, 0.f, 0.f, 0.f);
            int grow = brow + r;
            if (grow < M)
                v = *(const float4*)(A + (size_t)grow * 256 + kk + c4 * 4);
            As[(c4 * 4 + 0) * LDA + r] = v.x;
            As[(c4 * 4 + 1) * LDA + r] = v.y;
            As[(c4 * 4 + 2) * LDA + r] = v.z;
            As[(c4 * 4 + 3) * LDA + r] = v.w;
        }
        // load B tile (BK x BN) direct
#pragma unroll
        for (int it = 0; it < 2; it++) {
            int id = it * 256 + tid;
            int kr = id >> 5;                 // 0..15
            int c4 = id & 31;                 // 0..31
            *(float4*)(Bs + kr * BN + c4 * 4) =
                *(const float4*)(B + (size_t)(kk + kr) * 256 + bcol + c4 * 4);
        }
        __syncthreads();

#pragma unroll
        for (int k = 0; k < BK; k++) {
            float4 a0 = *(const float4*)(As + k * LDA + ty * 8);
            float4 a1 = *(const float4*)(As + k * LDA + ty * 8 + 4);
            float4 b0 = *(const float4*)(Bs + k * BN + tx * 8);
            float4 b1 = *(const float4*)(Bs + k * BN + tx * 8 + 4);
            float av[8] = {a0.x, a0.y, a0.z, a0.w, a1.x, a1.y, a1.z, a1.w};
            float bv[8] = {b0.x, b0.y, b0.z, b0.w, b1.x, b1.y, b1.z, b1.w};
#pragma unroll
            for (int i = 0; i < 8; i++)
#pragma unroll
                for (int j = 0; j < 8; j++) acc[i][j] += av[i] * bv[j];
        }
        __syncthreads();
    }

    // epilogue
#pragma unroll
    for (int i = 0; i < 8; i++) {
        int gr = brow + ty * 8 + i;
        if (gr >= M) continue;
        float dv = (MODE == 1) ? dinv[gr] : 0.0f;
#pragma unroll
        for (int j4 = 0; j4 < 2; j4++) {
            int gc = bcol + tx * 8 + j4 * 4;
            float4 v;
            v.x = acc[i][j4 * 4 + 0];
            v.y = acc[i][j4 * 4 + 1];
            v.z = acc[i][j4 * 4 + 2];
            v.w = acc[i][j4 * 4 + 3];
            if (MODE == 0) {
                float4 bb = *(const float4*)(bias + gc);
                v.x = fmaxf(v.x + bb.x, 0.f);
                v.y = fmaxf(v.y + bb.y, 0.f);
                v.z = fmaxf(v.z + bb.z, 0.f);
                v.w = fmaxf(v.w + bb.w, 0.f);
                *(float4*)(O1 + (size_t)gr * 256 + gc) = v;
            } else {
                v.x *= dv; v.y *= dv; v.z *= dv; v.w *= dv;
                *(float4*)(O1 + (size_t)gr * 256 + gc) = v;
                *(float4*)(O2 + (size_t)gr * 256 + gc) = v;
            }
        }
    }
}

// ---------------- edge scatter: acc[dst] += g[src] ----------------
// 64 threads per edge, one float4 each, vectorized reduction to L2.
__global__ void __launch_bounds__(256) scatter_edges(
    const int* __restrict__ src, const int* __restrict__ dst,
    const float* __restrict__ g, float* __restrict__ acc)
{
    long long gid = (long long)blockIdx.x * 256 + threadIdx.x;
    int e = (int)(gid >> 6);
    int c = (int)(gid & 63);
    if (e >= NE) return;
    int s = __ldg(src + e);
    int d = __ldg(dst + e);
    float4 v = *(const float4*)(g + (size_t)s * DD + c * 4);
    float* p = acc + (size_t)d * DD + c * 4;
    asm volatile("red.global.add.v4.f32 [%0], {%1,%2,%3,%4};"
                 :: "l"(p), "f"(v.x), "f"(v.y), "f"(v.z), "f"(v.w)
                 : "memory");
}

// ---------------- finalize: out = relu(dinv*acc + b) ----------------
__global__ void __launch_bounds__(256) finalize(
    const float* __restrict__ acc, const float* __restrict__ dinv,
    const float* __restrict__ b, float* __restrict__ out)
{
    int idx = blockIdx.x * blockDim.x + threadIdx.x;  // float4 units
    if (idx >= NN * (DD / 4)) return;
    int row = idx >> 6;
    int c4 = idx & 63;
    float dv = dinv[row];
    float4 v = ((const float4*)acc)[idx];
    float4 bb = ((const float4*)b)[c4];
    v.x = fmaxf(fmaf(v.x, dv, bb.x), 0.f);
    v.y = fmaxf(fmaf(v.y, dv, bb.y), 0.f);
    v.z = fmaxf(fmaf(v.z, dv, bb.z), 0.f);
    v.w = fmaxf(fmaf(v.w, dv, bb.w), 0.f);
    ((float4*)out)[idx] = v;
}

// ---------------- launch ----------------
extern "C" void kernel_launch(void* const* d_in, const int* in_sizes, int n_in,
                              void* d_out, int out_size)
{
    const float* input  = (const float*)d_in[0];
    const unsigned int* ei_words = (const unsigned int*)d_in[1];
    const float* weight = (const float*)d_in[2];
    const float* bias   = (const float*)d_in[3];
    const float* conv_w = (const float*)d_in[4];  // [2,256,256]
    const float* conv_b = (const float*)d_in[5];  // [2,256]
    float* out = (float*)d_out;

    float *xbuf, *gbuf, *accbuf, *deg;
    int *src, *dst;
    cudaGetSymbolAddress((void**)&xbuf, g_x);
    cudaGetSymbolAddress((void**)&gbuf, g_g);
    cudaGetSymbolAddress((void**)&accbuf, g_acc);
    cudaGetSymbolAddress((void**)&deg, g_deg);
    cudaGetSymbolAddress((void**)&src, g_src);
    cudaGetSymbolAddress((void**)&dst, g_dst);

    // normalize edge index dtype, build int32 src/dst, compute dinv
    detect_dtype<<<1, 256>>>(ei_words);
    deg_init<<<(NN + 255) / 256, 256>>>(deg);
    convert_and_count<<<(NE + 255) / 256, 256>>>(ei_words, src, dst, deg);
    deg_inv<<<(NN + 255) / 256, 256>>>(deg);

    dim3 ggrid(2, (NN + 127) / 128);

    // layer 0: x = relu(input @ weight + bias)
    sgemm<0><<<ggrid, 256>>>(input, weight, bias, nullptr, xbuf, nullptr, NN);

    const int scat_blocks = (int)(((long long)NE * 64 + 255) / 256);
    const int fin_blocks = (NN * 64 + 255) / 256;

    // conv 0
    sgemm<1><<<ggrid, 256>>>(xbuf, conv_w, nullptr, deg, gbuf, accbuf, NN);
    scatter_edges<<<scat_blocks, 256>>>(src, dst, gbuf, accbuf);
    finalize<<<fin_blocks, 256>>>(accbuf, deg, conv_b, xbuf);

    // conv 1
    sgemm<1><<<ggrid, 256>>>(xbuf, conv_w + 256 * 256, nullptr, deg, gbuf, accbuf, NN);
    scatter_edges<<<scat_blocks, 256>>>(src, dst, gbuf, accbuf);
    finalize<<<fin_blocks, 256>>>(accbuf, deg, conv_b + 256, out);
}

// round 3
// speedup vs baseline: 1.3018x; 1.3018x over previous
#include <cuda_runtime.h>

#define NN 50000
#define NE 800000
#define DD 256

// ---------------- scratch (no allocations allowed) ----------------
__device__ float g_x[NN * DD];     // current node features
__device__ float g_g[NN * DD];     // g = dinv * (x @ W)
__device__ float g_dinv[NN];
__device__ int   g_cnt[NN];        // in-degree (without self loop)
__device__ int   g_rowptr[NN + 1];
__device__ int   g_cursor[NN];
__device__ int   g_col[NE];        // CSR col = src per dst
__device__ int   g_srcbuf[NE];
__device__ int   g_dstbuf[NE];
__device__ int   g_is64;

// ---------------- edge-index dtype sniffing ----------------
__global__ void detect_dtype(const unsigned int* __restrict__ w) {
    __shared__ int any_nz;
    if (threadIdx.x == 0) any_nz = 0;
    __syncthreads();
    int nz = 0;
#pragma unroll
    for (int i = 0; i < 16; i++) {
        int idx = (threadIdx.x * 16 + i) * 2 + 1;  // odd dwords
        if (w[idx] != 0u) nz = 1;
    }
    if (nz) atomicOr(&any_nz, 1);
    __syncthreads();
    if (threadIdx.x == 0) g_is64 = any_nz ? 0 : 1;
}

__global__ void zero_cnt(int* cnt) {
    int i = blockIdx.x * blockDim.x + threadIdx.x;
    if (i < NN) cnt[i] = 0;
}

// convert to int32 src/dst and count in-degrees
__global__ void convert_and_count(const unsigned int* __restrict__ w,
                                  int* __restrict__ src, int* __restrict__ dst,
                                  int* __restrict__ cnt) {
    int e = blockIdx.x * blockDim.x + threadIdx.x;
    if (e >= NE) return;
    int s, d;
    if (g_is64) {
        s = (int)w[2 * e];
        d = (int)w[2 * NE + 2 * e];
    } else {
        s = (int)w[e];
        d = (int)w[NE + e];
    }
    src[e] = s;
    dst[e] = d;
    atomicAdd(&cnt[d], 1);
}

__global__ void deg_inv(const int* __restrict__ cnt, float* __restrict__ dinv) {
    int i = blockIdx.x * blockDim.x + threadIdx.x;
    if (i < NN) dinv[i] = rsqrtf((float)(cnt[i] + 1));
}

// exclusive scan of cnt -> row_ptr (+cursor copy), single block of 1024
__global__ void __launch_bounds__(1024) scan_rowptr(
    const int* __restrict__ cnt, int* __restrict__ row_ptr, int* __restrict__ cursor)
{
    __shared__ int partials[1024];
    const int t = threadIdx.x;
    const int CH = (NN + 1023) / 1024;  // 49
    int beg = t * CH;
    int s = 0;
    for (int i = 0; i < CH; i++) {
        int idx = beg + i;
        if (idx < NN) s += cnt[idx];
    }
    partials[t] = s;
    __syncthreads();
    // Hillis-Steele inclusive scan
    for (int off = 1; off < 1024; off <<= 1) {
        int v = (t >= off) ? partials[t - off] : 0;
        __syncthreads();
        partials[t] += v;
        __syncthreads();
    }
    int run = (t == 0) ? 0 : partials[t - 1];
    for (int i = 0; i < CH; i++) {
        int idx = beg + i;
        if (idx < NN) {
            row_ptr[idx] = run;
            cursor[idx] = run;
            run += cnt[idx];
        }
    }
    if (t == 1023) row_ptr[NN] = partials[1023];
}

__global__ void fill_csr(const int* __restrict__ src, const int* __restrict__ dst,
                         int* __restrict__ cursor, int* __restrict__ col) {
    int e = blockIdx.x * blockDim.x + threadIdx.x;
    if (e >= NE) return;
    int d = dst[e];
    int pos = atomicAdd(&cursor[d], 1);
    col[pos] = src[e];
}

// ---------------- SGEMM: C = A[M,256] @ B[256,256], reg-prefetch pipeline ----
// MODE 0: O1 = relu(C + bias)
// MODE 1: O1 = dinv[m] * C
template <int MODE>
__global__ void __launch_bounds__(256) sgemm(
    const float* __restrict__ A, const float* __restrict__ B,
    const float* __restrict__ bias, const float* __restrict__ dinv,
    float* __restrict__ O1, int M)
{
    constexpr int BM = 128, BN = 128, BK = 16, LDA = 132;
    __shared__ float As[BK * LDA];
    __shared__ float Bs[BK * BN];

    const int tid = threadIdx.x;
    const int tx = tid & 15;
    const int ty = tid >> 4;
    const int brow = blockIdx.y * BM;
    const int bcol = blockIdx.x * BN;

    // per-thread load coordinates (2 float4 for A, 2 for B)
    const int a_r0 = tid >> 2;             // it=0: rows 0..63
    const int a_c4 = tid & 3;
    const int b_kr0 = tid >> 5;            // it=0: k rows 0..7
    const int b_c4 = tid & 31;

    float4 pa[2], pb[2];

    auto ldg_tile = [&](int kk) {
#pragma unroll
        for (int it = 0; it < 2; it++) {
            int r = a_r0 + it * 64;
            int grow = brow + r;
            pa[it] = (grow < M) ? *(const float4*)(A + (size_t)grow * 256 + kk + a_c4 * 4)
                                : make_float4(0.f, 0.f, 0.f, 0.f);
            int kr = b_kr0 + it * 8;
            pb[it] = *(const float4*)(B + (size_t)(kk + kr) * 256 + bcol + b_c4 * 4);
        }
    };
    auto sts_tile = [&]() {
#pragma unroll
        for (int it = 0; it < 2; it++) {
            int r = a_r0 + it * 64;
            As[(a_c4 * 4 + 0) * LDA + r] = pa[it].x;
            As[(a_c4 * 4 + 1) * LDA + r] = pa[it].y;
            As[(a_c4 * 4 + 2) * LDA + r] = pa[it].z;
            As[(a_c4 * 4 + 3) * LDA + r] = pa[it].w;
            int kr = b_kr0 + it * 8;
            *(float4*)(Bs + kr * BN + b_c4 * 4) = pb[it];
        }
    };

    float acc[8][8];
#pragma unroll
    for (int i = 0; i < 8; i++)
#pragma unroll
        for (int j = 0; j < 8; j++) acc[i][j] = 0.0f;

    ldg_tile(0);
    sts_tile();
    __syncthreads();

    for (int kk = BK; kk <= 256; kk += BK) {
        if (kk < 256) ldg_tile(kk);  // prefetch next tile while computing
#pragma unroll
        for (int k = 0; k < BK; k++) {
            float4 a0 = *(const float4*)(As + k * LDA + ty * 8);
            float4 a1 = *(const float4*)(As + k * LDA + ty * 8 + 4);
            float4 b0 = *(const float4*)(Bs + k * BN + tx * 8);
            float4 b1 = *(const float4*)(Bs + k * BN + tx * 8 + 4);
            float av[8] = {a0.x, a0.y, a0.z, a0.w, a1.x, a1.y, a1.z, a1.w};
            float bv[8] = {b0.x, b0.y, b0.z, b0.w, b1.x, b1.y, b1.z, b1.w};
#pragma unroll
            for (int i = 0; i < 8; i++)
#pragma unroll
                for (int j = 0; j < 8; j++) acc[i][j] += av[i] * bv[j];
        }
        if (kk < 256) {
            __syncthreads();
            sts_tile();
            __syncthreads();
        }
    }

    // epilogue
#pragma unroll
    for (int i = 0; i < 8; i++) {
        int gr = brow + ty * 8 + i;
        if (gr >= M) continue;
        float dv = (MODE == 1) ? dinv[gr] : 0.0f;
#pragma unroll
        for (int j4 = 0; j4 < 2; j4++) {
            int gc = bcol + tx * 8 + j4 * 4;
            float4 v;
            v.x = acc[i][j4 * 4 + 0];
            v.y = acc[i][j4 * 4 + 1];
            v.z = acc[i][j4 * 4 + 2];
            v.w = acc[i][j4 * 4 + 3];
            if (MODE == 0) {
                float4 bb = *(const float4*)(bias + gc);
                v.x = fmaxf(v.x + bb.x, 0.f);
                v.y = fmaxf(v.y + bb.y, 0.f);
                v.z = fmaxf(v.z + bb.z, 0.f);
                v.w = fmaxf(v.w + bb.w, 0.f);
            } else {
                v.x *= dv; v.y *= dv; v.z *= dv; v.w *= dv;
            }
            *(float4*)(O1 + (size_t)gr * 256 + gc) = v;
        }
    }
}

// ---------------- CSR aggregate: out = relu(dinv*(g[n] + sum g[nbr]) + b) ----
// one warp per node; lane handles float4 columns lane and lane+32
__global__ void __launch_bounds__(256) aggregate(
    const int* __restrict__ row_ptr, const int* __restrict__ col,
    const float* __restrict__ g, const float* __restrict__ dinv,
    const float* __restrict__ b, float* __restrict__ out)
{
    int node = blockIdx.x * 8 + (threadIdx.x >> 5);
    if (node >= NN) return;
    int lane = threadIdx.x & 31;
    const float4* g4 = (const float4*)g;

    float4 a0 = g4[(size_t)node * 64 + lane];        // self loop
    float4 a1 = g4[(size_t)node * 64 + 32 + lane];

    int e = row_ptr[node];
    int end = row_ptr[node + 1];
    for (; e + 1 < end; e += 2) {
        int s0 = __ldg(col + e);
        int s1 = __ldg(col + e + 1);
        float4 v0 = g4[(size_t)s0 * 64 + lane];
        float4 v1 = g4[(size_t)s0 * 64 + 32 + lane];
        float4 w0 = g4[(size_t)s1 * 64 + lane];
        float4 w1 = g4[(size_t)s1 * 64 + 32 + lane];
        a0.x += v0.x + w0.x; a0.y += v0.y + w0.y; a0.z += v0.z + w0.z; a0.w += v0.w + w0.w;
        a1.x += v1.x + w1.x; a1.y += v1.y + w1.y; a1.z += v1.z + w1.z; a1.w += v1.w + w1.w;
    }
    if (e < end) {
        int s0 = __ldg(col + e);
        float4 v0 = g4[(size_t)s0 * 64 + lane];
        float4 v1 = g4[(size_t)s0 * 64 + 32 + lane];
        a0.x += v0.x; a0.y += v0.y; a0.z += v0.z; a0.w += v0.w;
        a1.x += v1.x; a1.y += v1.y; a1.z += v1.z; a1.w += v1.w;
    }

    float dv = dinv[node];
    float4 b0 = ((const float4*)b)[lane];
    float4 b1 = ((const float4*)b)[32 + lane];
    a0.x = fmaxf(fmaf(a0.x, dv, b0.x), 0.f);
    a0.y = fmaxf(fmaf(a0.y, dv, b0.y), 0.f);
    a0.z = fmaxf(fmaf(a0.z, dv, b0.z), 0.f);
    a0.w = fmaxf(fmaf(a0.w, dv, b0.w), 0.f);
    a1.x = fmaxf(fmaf(a1.x, dv, b1.x), 0.f);
    a1.y = fmaxf(fmaf(a1.y, dv, b1.y), 0.f);
    a1.z = fmaxf(fmaf(a1.z, dv, b1.z), 0.f);
    a1.w = fmaxf(fmaf(a1.w, dv, b1.w), 0.f);
    ((float4*)out)[(size_t)node * 64 + lane] = a0;
    ((float4*)out)[(size_t)node * 64 + 32 + lane] = a1;
}

// ---------------- launch ----------------
extern "C" void kernel_launch(void* const* d_in, const int* in_sizes, int n_in,
                              void* d_out, int out_size)
{
    const float* input  = (const float*)d_in[0];
    const unsigned int* ei_words = (const unsigned int*)d_in[1];
    const float* weight = (const float*)d_in[2];
    const float* bias   = (const float*)d_in[3];
    const float* conv_w = (const float*)d_in[4];  // [2,256,256]
    const float* conv_b = (const float*)d_in[5];  // [2,256]
    float* out = (float*)d_out;

    float *xbuf, *gbuf, *dinv;
    int *cnt, *row_ptr, *cursor, *col, *src, *dst;
    cudaGetSymbolAddress((void**)&xbuf, g_x);
    cudaGetSymbolAddress((void**)&gbuf, g_g);
    cudaGetSymbolAddress((void**)&dinv, g_dinv);
    cudaGetSymbolAddress((void**)&cnt, g_cnt);
    cudaGetSymbolAddress((void**)&row_ptr, g_rowptr);
    cudaGetSymbolAddress((void**)&cursor, g_cursor);
    cudaGetSymbolAddress((void**)&col, g_col);
    cudaGetSymbolAddress((void**)&src, g_srcbuf);
    cudaGetSymbolAddress((void**)&dst, g_dstbuf);

    // edge prep + CSR build (shared by both conv layers)
    detect_dtype<<<1, 256>>>(ei_words);
    zero_cnt<<<(NN + 255) / 256, 256>>>(cnt);
    convert_and_count<<<(NE + 255) / 256, 256>>>(ei_words, src, dst, cnt);
    deg_inv<<<(NN + 255) / 256, 256>>>(cnt, dinv);
    scan_rowptr<<<1, 1024>>>(cnt, row_ptr, cursor);
    fill_csr<<<(NE + 255) / 256, 256>>>(src, dst, cursor, col);

    dim3 ggrid(2, (NN + 127) / 128);
    const int agg_blocks = (NN + 7) / 8;

    // layer 0: x = relu(input @ weight + bias)
    sgemm<0><<<ggrid, 256>>>(input, weight, bias, nullptr, xbuf, NN);

    // conv 0
    sgemm<1><<<ggrid, 256>>>(xbuf, conv_w, nullptr, dinv, gbuf, NN);
    aggregate<<<agg_blocks, 256>>>(row_ptr, col, gbuf, dinv, conv_b, xbuf);

    // conv 1
    sgemm<1><<<ggrid, 256>>>(xbuf, conv_w + 256 * 256, nullptr, dinv, gbuf, NN);
    aggregate<<<agg_blocks, 256>>>(row_ptr, col, gbuf, dinv, conv_b + 256, out);
}